// round 2
// baseline (speedup 1.0000x reference)
#include <cuda_runtime.h>

// Problem constants
#define NB_UP    8      // electrons per spin channel
#define NMO_     40     // molecular orbitals
#define NELEC_   16     // total electrons (2 * NB_UP)

// One block per walker (batch b), one thread per CI configuration c.
// Each thread gathers two 8x8 Slater matrices from shared memory and
// computes det(up)*det(down) via fully-unrolled register LU with
// partial pivoting (predicated bubble-max swaps, sign tracked).
__global__ __launch_bounds__(256, 2)
void slater_det_kernel(const float* __restrict__ mo,
                       const int*   __restrict__ cup,
                       const int*   __restrict__ cdown,
                       float*       __restrict__ out,
                       int nconf)
{
    __shared__ float mo_sh[NELEC_ * NMO_];   // 640 floats = 2560 B

    const int b = blockIdx.x;
    const int t = threadIdx.x;

    // Cooperative vectorized stage of this walker's MO block (16x40 f32).
    // 640 floats = 160 float4 loads; base offset b*2560 B is 16B-aligned.
    {
        const float4* src = reinterpret_cast<const float4*>(mo + (size_t)b * (NELEC_ * NMO_));
        float4*       dst = reinterpret_cast<float4*>(mo_sh);
        if (t < (NELEC_ * NMO_) / 4) dst[t] = src[t];
    }
    __syncthreads();

    const int c = t;
    if (c >= nconf) return;

    float result = 1.0f;

    #pragma unroll 1   // keep code size down: one copy of gather+LU for both spins
    for (int s = 0; s < 2; ++s) {
        const int*   cw  = ((s == 0) ? cup : cdown) + c * NB_UP;
        const float* msh = mo_sh + s * (NB_UP * NMO_);

        // Gather the 8x8 Slater matrix: a[i][j] = mo[b, s*8+i, cw[j]]
        float a[NB_UP][NB_UP];
        #pragma unroll
        for (int j = 0; j < NB_UP; ++j) {
            const int col = __ldg(&cw[j]);
            #pragma unroll
            for (int i = 0; i < NB_UP; ++i)
                a[i][j] = msh[i * NMO_ + col];
        }

        // In-register LU with partial pivoting, fully unrolled (static indices
        // only, so the matrix stays in registers — no local-memory spills).
        float det = 1.0f;
        #pragma unroll
        for (int k = 0; k < NB_UP; ++k) {
            // Bubble the max-|.| pivot of column k (rows k..7) into row k.
            // Each realized swap is a transposition -> flip det sign.
            #pragma unroll
            for (int r = k + 1; r < NB_UP; ++r) {
                const bool sw = fabsf(a[r][k]) > fabsf(a[k][k]);
                det = sw ? -det : det;
                #pragma unroll
                for (int j = k; j < NB_UP; ++j) {
                    const float t0 = a[k][j];
                    const float t1 = a[r][j];
                    a[k][j] = sw ? t1 : t0;
                    a[r][j] = sw ? t0 : t1;
                }
            }
            const float piv = a[k][k];
            det *= piv;
            const float inv = __frcp_rn(piv);
            #pragma unroll
            for (int r = k + 1; r < NB_UP; ++r) {
                const float f = a[r][k] * inv;
                #pragma unroll
                for (int j = k + 1; j < NB_UP; ++j)
                    a[r][j] = fmaf(-f, a[k][j], a[r][j]);
            }
        }
        result *= det;
    }

    out[(size_t)b * nconf + c] = result;
}

extern "C" void kernel_launch(void* const* d_in, const int* in_sizes, int n_in,
                              void* d_out, int out_size)
{
    const float* mo    = (const float*)d_in[0];  // (B, 16, 40) f32
    const int*   cup   = (const int*)  d_in[1];  // (C, 8) i32
    const int*   cdown = (const int*)  d_in[2];  // (C, 8) i32
    float*       out   = (float*)d_out;          // (B, C) f32

    const int B = in_sizes[0] / (NELEC_ * NMO_);
    const int C = in_sizes[1] / NB_UP;

    slater_det_kernel<<<B, C>>>(mo, cup, cdown, out, C);
}